// round 1
// baseline (speedup 1.0000x reference)
#include <cuda_runtime.h>

#define DD 8
#define BB 4096
#define VV 1024
#define K_SEL 102
#define THREADS 256

__device__ int g_samples[DD * BB];

__device__ __forceinline__ unsigned fkey(float f) {
    unsigned b = __float_as_uint(f);
    return (b & 0x80000000u) ? ~b : (b | 0x80000000u);
}
__device__ __forceinline__ float keyf(unsigned k) {
    unsigned b = (k & 0x80000000u) ? (k & 0x7FFFFFFFu) : ~k;
    return __uint_as_float(b);
}

__global__ __launch_bounds__(THREADS)
void decode_kernel(const float* __restrict__ logits,
                   const float* __restrict__ uin,
                   const int* __restrict__ curv,
                   float* __restrict__ out_probs,
                   int write_probs)
{
    const int r    = blockIdx.x;            // r = d*B + b
    const int tid  = threadIdx.x;
    const int lane = tid & 31;
    const int wid  = tid >> 5;
    const float NEG = __int_as_float(0xff800000); // -inf
    const size_t base = (size_t)r * VV;
    const int cur = curv[r];

    __shared__ int sh_hist[256];
    __shared__ int sh_wsum[8];
    __shared__ unsigned sh_sel;
    __shared__ int sh_krem;
    __shared__ unsigned sh_maxkey;
    __shared__ unsigned long long sh_best;
    __shared__ float sh_red[8];
    __shared__ float sh_logZ;

    if (tid == 0) { sh_maxkey = 0u; sh_best = 0ull; }

    // ---- load (logits + u read exactly once, vectorized) ----
    float4 lv = ((const float4*)(logits + base))[tid];
    float4 uv = ((const float4*)(uin    + base))[tid];
    float vals[4] = {lv.x, lv.y, lv.z, lv.w};
    float us[4]   = {uv.x, uv.y, uv.z, uv.w};
    const int vbase = tid * 4;

    unsigned keys[4];
#pragma unroll
    for (int j = 0; j < 4; ++j) {
        int v = vbase + j;
        if (v < cur || v == 0) vals[j] = NEG;
        keys[j] = fkey(vals[j]);
    }

    // ---- exact k-th largest via 4x8-bit radix select ----
    unsigned prefix = 0u, pmask = 0u;
    int krem = K_SEL;
#pragma unroll
    for (int pass = 0; pass < 4; ++pass) {
        const int shift = 24 - 8 * pass;
        sh_hist[tid] = 0;
        __syncthreads();
#pragma unroll
        for (int j = 0; j < 4; ++j)
            if ((keys[j] & pmask) == prefix)
                atomicAdd(&sh_hist[(keys[j] >> shift) & 0xFFu], 1);
        __syncthreads();
        int cnt = sh_hist[tid];
        int x = cnt;                       // warp suffix scan (inclusive)
#pragma unroll
        for (int off = 1; off < 32; off <<= 1) {
            int y = __shfl_down_sync(0xffffffffu, x, off);
            if (lane + off < 32) x += y;
        }
        if (lane == 0) sh_wsum[wid] = x;   // warp total
        __syncthreads();
        int tail = 0;
#pragma unroll
        for (int w = 1; w < 8; ++w)
            if (w > wid) tail += sh_wsum[w];
        int suffix = x + tail;             // count of keys in buckets >= tid (within prefix)
        if (suffix >= krem && (suffix - cnt) < krem) {
            sh_sel  = (unsigned)tid;
            sh_krem = krem - (suffix - cnt);
        }
        __syncthreads();
        prefix |= sh_sel << shift;
        pmask  |= 0xFFu << shift;
        krem    = sh_krem;
        // next-pass writes to sh_sel/sh_krem are fenced by two barriers above
    }
    const float kth = keyf(prefix);

    // ---- row max (keys are monotone; atomicMax is exact/associative) ----
    unsigned lmax = max(max(keys[0], keys[1]), max(keys[2], keys[3]));
    atomicMax(&sh_maxkey, lmax);
    __syncthreads();
    const float m = keyf(sh_maxkey);

    // ---- sum(exp(x - m)) over kept, fixed-order tree (deterministic) ----
    float s = 0.f;
#pragma unroll
    for (int j = 0; j < 4; ++j)
        if (vals[j] >= kth) s += expf(vals[j] - m);
#pragma unroll
    for (int off = 16; off >= 1; off >>= 1)
        s += __shfl_down_sync(0xffffffffu, s, off);
    if (lane == 0) sh_red[wid] = s;
    __syncthreads();
    if (tid == 0) {
        float t = 0.f;
#pragma unroll
        for (int w = 0; w < 8; ++w) t += sh_red[w];
        sh_logZ = m + logf(t);
    }
    __syncthreads();
    const float logZ = sh_logZ;

    // ---- probs out + Gumbel argmax (first-index tie-break) ----
    float p[4];
    unsigned long long best = 0ull;
#pragma unroll
    for (int j = 0; j < 4; ++j) {
        bool kept = (vals[j] >= kth);
        float lp = vals[j] - logZ;          // logp (finite only when kept)
        p[j] = kept ? expf(lp) : 0.f;
        if (kept) {
            float g  = -logf(-logf(us[j] + 1e-20f) + 1e-20f);
            float sc = lp + g;              // same expression as reference
            unsigned long long k64 =
                ((unsigned long long)fkey(sc) << 32) |
                (unsigned long long)(0xFFFFFFFFu - (unsigned)(vbase + j));
            best = (k64 > best) ? k64 : best;
        }
    }
    if (best) atomicMax(&sh_best, best);
    if (write_probs)
        ((float4*)(out_probs + base))[tid] = make_float4(p[0], p[1], p[2], p[3]);
    __syncthreads();
    if (tid == 0)
        g_samples[r] = (int)(0xFFFFFFFFu - (unsigned)(sh_best & 0xFFFFFFFFull));
}

__global__ void tokens_kernel(float* __restrict__ out_tok)
{
    int i = blockIdx.x * blockDim.x + threadIdx.x;   // i in [0, B*D)
    if (i >= BB * DD) return;
    int b = i / DD, d = i % DD;
    int s0 = g_samples[b];            // field 0 sample for stream b
    int sd = g_samples[d * BB + b];
    int val = (d == 0 || s0 == 1) ? sd : 0;   // NOTE_TYPE == 1
    out_tok[i] = (float)val;                  // tokens.T flattened [B,D]
}

extern "C" void kernel_launch(void* const* d_in, const int* in_sizes, int n_in,
                              void* d_out, int out_size)
{
    const float* logits = (const float*)d_in[0];
    const float* uin    = (const float*)d_in[1];
    const int*   curv   = (const int*)d_in[2];
    float* out = (float*)d_out;

    const size_t probsN = (size_t)DD * BB * VV;
    const size_t tokN   = (size_t)BB * DD;

    float* out_tok = nullptr;
    float* out_probs = nullptr;
    if ((size_t)out_size >= probsN + tokN) {        // concat: tokens.T then probs
        out_tok = out; out_probs = out + tokN;
    } else if ((size_t)out_size >= probsN) {        // probs only
        out_probs = out;
    } else {                                        // tokens only
        out_tok = out;
    }

    decode_kernel<<<DD * BB, THREADS>>>(logits, uin, curv,
                                        out_probs ? out_probs : out,
                                        out_probs != nullptr ? 1 : 0);
    if (out_tok)
        tokens_kernel<<<(BB * DD + 255) / 256, 256>>>(out_tok);
}

// round 2
// speedup vs baseline: 1.0016x; 1.0016x over previous
#include <cuda_runtime.h>

#define DD 8
#define BB 4096
#define VV 1024
#define K_SEL 102
#define THREADS 256

__device__ int g_samples[DD * BB];

__device__ __forceinline__ unsigned fkey(float f) {
    unsigned b = __float_as_uint(f);
    return (b & 0x80000000u) ? ~b : (b | 0x80000000u);
}
__device__ __forceinline__ float keyf(unsigned k) {
    unsigned b = (k & 0x80000000u) ? (k & 0x7FFFFFFFu) : ~k;
    return __uint_as_float(b);
}

__global__ __launch_bounds__(THREADS)
void decode_kernel(const float* __restrict__ logits,
                   const float* __restrict__ uin,
                   const int* __restrict__ curv,
                   float* __restrict__ out_probs,
                   int write_probs)
{
    const int r    = blockIdx.x;            // r = d*B + b
    const int tid  = threadIdx.x;
    const int lane = tid & 31;
    const int wid  = tid >> 5;
    const float NEG = __int_as_float(0xff800000); // -inf
    const size_t base = (size_t)r * VV;
    const int cur = curv[r];

    __shared__ int sh_hist[256];
    __shared__ int sh_wsum[8];
    __shared__ unsigned sh_sel;
    __shared__ int sh_krem;
    __shared__ unsigned sh_maxkey;
    __shared__ unsigned long long sh_best;
    __shared__ float sh_red[8];
    __shared__ float sh_logZ;

    if (tid == 0) { sh_maxkey = 0u; sh_best = 0ull; }

    // ---- load (logits + u read exactly once, vectorized) ----
    float4 lv = ((const float4*)(logits + base))[tid];
    float4 uv = ((const float4*)(uin    + base))[tid];
    float vals[4] = {lv.x, lv.y, lv.z, lv.w};
    float us[4]   = {uv.x, uv.y, uv.z, uv.w};
    const int vbase = tid * 4;

    unsigned keys[4];
#pragma unroll
    for (int j = 0; j < 4; ++j) {
        int v = vbase + j;
        if (v < cur || v == 0) vals[j] = NEG;
        keys[j] = fkey(vals[j]);
    }

    // ---- exact k-th largest via 4x8-bit radix select ----
    unsigned prefix = 0u, pmask = 0u;
    int krem = K_SEL;
#pragma unroll
    for (int pass = 0; pass < 4; ++pass) {
        const int shift = 24 - 8 * pass;
        sh_hist[tid] = 0;
        __syncthreads();
#pragma unroll
        for (int j = 0; j < 4; ++j)
            if ((keys[j] & pmask) == prefix)
                atomicAdd(&sh_hist[(keys[j] >> shift) & 0xFFu], 1);
        __syncthreads();
        int cnt = sh_hist[tid];
        int x = cnt;                       // warp suffix scan (inclusive)
#pragma unroll
        for (int off = 1; off < 32; off <<= 1) {
            int y = __shfl_down_sync(0xffffffffu, x, off);
            if (lane + off < 32) x += y;
        }
        if (lane == 0) sh_wsum[wid] = x;   // warp total
        __syncthreads();
        int tail = 0;
#pragma unroll
        for (int w = 1; w < 8; ++w)
            if (w > wid) tail += sh_wsum[w];
        int suffix = x + tail;             // count of keys in buckets >= tid (within prefix)
        if (suffix >= krem && (suffix - cnt) < krem) {
            sh_sel  = (unsigned)tid;
            sh_krem = krem - (suffix - cnt);
        }
        __syncthreads();
        prefix |= sh_sel << shift;
        pmask  |= 0xFFu << shift;
        krem    = sh_krem;
        // next-pass writes to sh_sel/sh_krem are fenced by two barriers above
    }
    const float kth = keyf(prefix);

    // ---- row max (keys are monotone; atomicMax is exact/associative) ----
    unsigned lmax = max(max(keys[0], keys[1]), max(keys[2], keys[3]));
    atomicMax(&sh_maxkey, lmax);
    __syncthreads();
    const float m = keyf(sh_maxkey);

    // ---- sum(exp(x - m)) over kept, fixed-order tree (deterministic) ----
    float s = 0.f;
#pragma unroll
    for (int j = 0; j < 4; ++j)
        if (vals[j] >= kth) s += expf(vals[j] - m);
#pragma unroll
    for (int off = 16; off >= 1; off >>= 1)
        s += __shfl_down_sync(0xffffffffu, s, off);
    if (lane == 0) sh_red[wid] = s;
    __syncthreads();
    if (tid == 0) {
        float t = 0.f;
#pragma unroll
        for (int w = 0; w < 8; ++w) t += sh_red[w];
        sh_logZ = m + logf(t);
    }
    __syncthreads();
    const float logZ = sh_logZ;

    // ---- probs out + Gumbel argmax (first-index tie-break) ----
    float p[4];
    unsigned long long best = 0ull;
#pragma unroll
    for (int j = 0; j < 4; ++j) {
        bool kept = (vals[j] >= kth);
        float lp = vals[j] - logZ;          // logp (finite only when kept)
        p[j] = kept ? expf(lp) : 0.f;
        if (kept) {
            float g  = -logf(-logf(us[j] + 1e-20f) + 1e-20f);
            float sc = lp + g;              // same expression as reference
            unsigned long long k64 =
                ((unsigned long long)fkey(sc) << 32) |
                (unsigned long long)(0xFFFFFFFFu - (unsigned)(vbase + j));
            best = (k64 > best) ? k64 : best;
        }
    }
    if (best) atomicMax(&sh_best, best);
    if (write_probs)
        ((float4*)(out_probs + base))[tid] = make_float4(p[0], p[1], p[2], p[3]);
    __syncthreads();
    if (tid == 0)
        g_samples[r] = (int)(0xFFFFFFFFu - (unsigned)(sh_best & 0xFFFFFFFFull));
}

__global__ void tokens_kernel(float* __restrict__ out_tok)
{
    int i = blockIdx.x * blockDim.x + threadIdx.x;   // i in [0, B*D)
    if (i >= BB * DD) return;
    int b = i / DD, d = i % DD;
    int s0 = g_samples[b];            // field 0 sample for stream b
    int sd = g_samples[d * BB + b];
    int val = (d == 0 || s0 == 1) ? sd : 0;   // NOTE_TYPE == 1
    out_tok[i] = (float)val;                  // tokens.T flattened [B,D]
}

extern "C" void kernel_launch(void* const* d_in, const int* in_sizes, int n_in,
                              void* d_out, int out_size)
{
    const float* logits = (const float*)d_in[0];
    const float* uin    = (const float*)d_in[1];
    const int*   curv   = (const int*)d_in[2];
    float* out = (float*)d_out;

    const size_t probsN = (size_t)DD * BB * VV;
    const size_t tokN   = (size_t)BB * DD;

    float* out_tok = nullptr;
    float* out_probs = nullptr;
    if ((size_t)out_size >= probsN + tokN) {        // concat: tokens.T then probs
        out_tok = out; out_probs = out + tokN;
    } else if ((size_t)out_size >= probsN) {        // probs only
        out_probs = out;
    } else {                                        // tokens only
        out_tok = out;
    }

    decode_kernel<<<DD * BB, THREADS>>>(logits, uin, curv,
                                        out_probs ? out_probs : out,
                                        out_probs != nullptr ? 1 : 0);
    if (out_tok)
        tokens_kernel<<<(BB * DD + 255) / 256, 256>>>(out_tok);
}